// round 4
// baseline (speedup 1.0000x reference)
#include <cuda_runtime.h>
#include <cstdint>

// ---------------------------------------------------------------------------
// 2-layer GCN:  out = Â( relu( Â(xW1)+b1 ) W2 ) + b2,  Â = D^-1/2 (A+I) D^-1/2
// edge_index is INT32 on device (JAX x64 disabled downcasts jnp.int64->int32).
// Â applied as: self-loop term (h[v]*dis[v]^2 + b) + edge scatter (atomics).
// Scratch in __device__ globals referenced directly from device code.
// ---------------------------------------------------------------------------

static constexpr int NN = 100000;
static constexpr int NE = 1600000;

__device__ float g_h1[(size_t)NN * 128];   // x @ W1
__device__ float g_a1[(size_t)NN * 128];   // Â h1 + b1   (pre-ReLU)
__device__ float g_h2[(size_t)NN * 64];    // relu(a1) @ W2
__device__ float g_dis[NN];                // deg^-1/2
__device__ int   g_deg[NN];

// ---------------------------------------------------------------------------
// degree / normalization
// ---------------------------------------------------------------------------
__global__ void k_deg_init() {
    int i = blockIdx.x * blockDim.x + threadIdx.x;
    if (i < NN) g_deg[i] = 1;              // self-loop
}

__global__ void k_deg_count(const int* __restrict__ ei) {
    int e = blockIdx.x * blockDim.x + threadIdx.x;
    if (e < NE) atomicAdd(&g_deg[ei[NE + e]], 1);
}

__global__ void k_dis() {
    int i = blockIdx.x * blockDim.x + threadIdx.x;
    if (i < NN) g_dis[i] = rsqrtf((float)g_deg[i]);
}

// ---------------------------------------------------------------------------
// SIMT fp32 GEMM: C[M,BN] = A[M,128] @ W[128,BN], K chunked by 32.
// 128 threads, 8x8 register tile per thread; rows interleaved (i*NTY+ty),
// PADK=33 for conflict-free A reads. Static smem only.
// SRC=0: A = x (param),    C = g_h1
// SRC=1: A = g_a1 (+ReLU), C = g_h2
// ---------------------------------------------------------------------------
template <int BM, int BN, bool RELU, int SRC>
__global__ void __launch_bounds__(128)
k_gemm(const float* __restrict__ Ap, const float* __restrict__ W, int M) {
    constexpr int K    = 128;
    constexpr int KC   = 32;
    constexpr int PADK = KC + 1;
    constexpr int NTX  = BN / 8;
    constexpr int NTY  = BM / 8;
    static_assert(NTX * NTY == 128, "128 threads");

    __shared__ float As[BM * PADK];
    __shared__ float Ws[KC * BN];

    const float* A = (SRC == 0) ? Ap : g_a1;
    float*       C = (SRC == 0) ? g_h1 : g_h2;

    const int tid = threadIdx.x;
    const int tx  = tid % NTX;
    const int ty  = tid / NTX;
    const int rowbase = blockIdx.x * BM;

    float acc[8][8] = {};

    for (int kk = 0; kk < K; kk += KC) {
        // --- load A chunk (BM x 32), zero-fill rows >= M ---
        {
            constexpr int PT = (BM * KC / 4) / 128;
            const float4* A4 = (const float4*)A;
#pragma unroll
            for (int t = 0; t < PT; t++) {
                int f  = tid + t * 128;
                int r  = f >> 3;                 // 8 float4 per 32-col row
                int c4 = f & 7;
                int grow = rowbase + r;
                float4 v = make_float4(0.f, 0.f, 0.f, 0.f);
                if (grow < M) v = A4[(size_t)grow * 32 + (kk >> 2) + c4];
                if (RELU) {
                    v.x = fmaxf(v.x, 0.f); v.y = fmaxf(v.y, 0.f);
                    v.z = fmaxf(v.z, 0.f); v.w = fmaxf(v.w, 0.f);
                }
                float* dst = As + r * PADK + c4 * 4;
                dst[0] = v.x; dst[1] = v.y; dst[2] = v.z; dst[3] = v.w;
            }
        }
        // --- load W chunk (32 x BN) ---
        {
            constexpr int PT = (KC * BN / 4) / 128;
            const float4* W4  = (const float4*)(W + (size_t)kk * BN);
            float4*       Ws4 = (float4*)Ws;
#pragma unroll
            for (int t = 0; t < PT; t++)
                Ws4[tid + t * 128] = W4[tid + t * 128];
        }
        __syncthreads();

#pragma unroll
        for (int k = 0; k < KC; k++) {
            float a[8];
#pragma unroll
            for (int i = 0; i < 8; i++)
                a[i] = As[(i * NTY + ty) * PADK + k];
            const float4 b0 = ((const float4*)(Ws + k * BN))[tx * 2];
            const float4 b1 = ((const float4*)(Ws + k * BN))[tx * 2 + 1];
            const float b[8] = {b0.x, b0.y, b0.z, b0.w, b1.x, b1.y, b1.z, b1.w};
#pragma unroll
            for (int i = 0; i < 8; i++)
#pragma unroll
                for (int j = 0; j < 8; j++)
                    acc[i][j] = fmaf(a[i], b[j], acc[i][j]);
        }
        __syncthreads();
    }

#pragma unroll
    for (int i = 0; i < 8; i++) {
        int grow = rowbase + i * NTY + ty;
        if (grow < M) {
            float4* Crow = (float4*)(C + (size_t)grow * BN);
            Crow[tx * 2]     = make_float4(acc[i][0], acc[i][1], acc[i][2], acc[i][3]);
            Crow[tx * 2 + 1] = make_float4(acc[i][4], acc[i][5], acc[i][6], acc[i][7]);
        }
    }
}

// ---------------------------------------------------------------------------
// self-loop init: out[v,:] = h[v,:] * dis[v]^2 + b[:]
// C=128: g_h1 -> g_a1;  C=64: g_h2 -> outp (d_out)
// ---------------------------------------------------------------------------
template <int C>
__global__ void k_selfinit(const float* __restrict__ b, float* __restrict__ outp) {
    constexpr int C4 = C / 4;
    const float* h;
    float*       out;
    if constexpr (C == 128) { h = g_h1; out = g_a1; }
    else                    { h = g_h2; out = outp; }

    int idx = blockIdx.x * blockDim.x + threadIdx.x;
    if (idx >= NN * C4) return;
    int node = idx / C4;
    int c4   = idx % C4;
    float s = g_dis[node];
    s *= s;
    float4 v  = ((const float4*)h)[idx];
    float4 bb = ((const float4*)b)[c4];
    ((float4*)out)[idx] =
        make_float4(fmaf(v.x, s, bb.x), fmaf(v.y, s, bb.y),
                    fmaf(v.z, s, bb.z), fmaf(v.w, s, bb.w));
}

// ---------------------------------------------------------------------------
// edge scatter: out[dst,:] += dis[src]*dis[dst] * h[src,:]
// one warp per edge, coalesced scalar float atomics (RED.E.ADD.F32)
// ---------------------------------------------------------------------------
template <int C>
__global__ void k_edge(const int* __restrict__ ei, float* __restrict__ outp) {
    constexpr int CHUNKS = C / 32;
    const float* h;
    float*       out;
    if constexpr (C == 128) { h = g_h1; out = g_a1; }
    else                    { h = g_h2; out = outp; }

    const int lane = threadIdx.x & 31;
    const int wid  = (blockIdx.x * blockDim.x + threadIdx.x) >> 5;
    const int nw   = (gridDim.x * blockDim.x) >> 5;

    for (int e = wid; e < NE; e += nw) {
        const int s = ei[e];
        const int d = ei[NE + e];
        const float nrm = g_dis[s] * g_dis[d];
        const float* hs = h + (size_t)s * C + lane;
        float*       od = out + (size_t)d * C + lane;
#pragma unroll
        for (int c = 0; c < CHUNKS; c++) {
            float v = hs[c * 32];
            atomicAdd(od + c * 32, v * nrm);
        }
    }
}

// ---------------------------------------------------------------------------
extern "C" void kernel_launch(void* const* d_in, const int* in_sizes, int n_in,
                              void* d_out, int out_size) {
    (void)in_sizes; (void)n_in; (void)out_size;
    const float* x  = (const float*)d_in[0];
    const int*   ei = (const int*)d_in[1];     // int32! (JAX x64 disabled)
    const float* W1 = (const float*)d_in[2];
    const float* b1 = (const float*)d_in[3];
    const float* W2 = (const float*)d_in[4];
    const float* b2 = (const float*)d_in[5];
    float* out = (float*)d_out;

    // --- normalization ---
    k_deg_init<<<(NN + 255) / 256, 256>>>();
    k_deg_count<<<(NE + 255) / 256, 256>>>(ei);
    k_dis<<<(NN + 255) / 256, 256>>>();

    // --- layer 1: h1 = x@W1 ; a1 = selfloop(h1)+b1 ; a1 += scatter(h1) ---
    k_gemm<64, 128, false, 0><<<(NN + 63) / 64, 128>>>(x, W1, NN);
    k_selfinit<128><<<(NN * 32 + 255) / 256, 256>>>(b1, nullptr);
    k_edge<128><<<1184, 256>>>(ei, nullptr);

    // --- layer 2: h2 = relu(a1)@W2 ; out = selfloop(h2)+b2 ; out += scatter(h2) ---
    k_gemm<128, 64, true, 1><<<(NN + 127) / 128, 128>>>(nullptr, W2, NN);
    k_selfinit<64><<<(NN * 16 + 255) / 256, 256>>>(b2, out);
    k_edge<64><<<1184, 256>>>(ei, out);
}

// round 5
// speedup vs baseline: 1.1137x; 1.1137x over previous
#include <cuda_runtime.h>
#include <cstdint>

// ---------------------------------------------------------------------------
// 2-layer GCN:  out = Â( relu( Â(xW1)+b1 ) W2 ) + b2,  Â = D^-1/2 (A+I) D^-1/2
// edge_index is INT32 on device. Self-loop term fused into GEMM epilogue;
// edge scatter uses vectorized L2 reductions (red.global.add.v4/.v2.f32).
// ---------------------------------------------------------------------------

static constexpr int NN = 100000;
static constexpr int NE = 1600000;

__device__ float g_h1[(size_t)NN * 128];   // x @ W1
__device__ float g_a1[(size_t)NN * 128];   // Â h1 + b1   (pre-ReLU)
__device__ float g_h2[(size_t)NN * 64];    // relu(a1) @ W2
__device__ float g_dis[NN];                // deg^-1/2
__device__ int   g_deg[NN];

// ---------------------------------------------------------------------------
// degree / normalization
// ---------------------------------------------------------------------------
__global__ void k_deg_init() {
    int i = blockIdx.x * blockDim.x + threadIdx.x;
    if (i < NN) g_deg[i] = 1;              // self-loop
}

__global__ void k_deg_count(const int* __restrict__ ei) {
    int e = blockIdx.x * blockDim.x + threadIdx.x;
    if (e < NE) atomicAdd(&g_deg[ei[NE + e]], 1);
}

__global__ void k_dis() {
    int i = blockIdx.x * blockDim.x + threadIdx.x;
    if (i < NN) g_dis[i] = rsqrtf((float)g_deg[i]);
}

// ---------------------------------------------------------------------------
// SIMT fp32 GEMM with fused self-loop epilogue.
//   h   = A @ W                       -> H   (raw, needed by edge gather)
//   o2  = h * dis[row]^2 + bias       -> O2  (scatter target, fully init'd)
// As tile is K-MAJOR so the a-fragment is 2 x LDS.128 per k.
// SRC=0: A = x (param),    H = g_h1, O2 = g_a1
// SRC=1: A = g_a1 (+ReLU), H = g_h2, O2 = d_out
// ---------------------------------------------------------------------------
template <int BM, int BN, bool RELU, int SRC>
__global__ void __launch_bounds__(128)
k_gemm(const float* __restrict__ Ap, const float* __restrict__ W,
       const float* __restrict__ bias, float* __restrict__ o2p, int M) {
    constexpr int K   = 128;
    constexpr int KC  = 32;
    constexpr int SA  = BM + 4;          // k-major row stride (16B-aligned, staggered)
    constexpr int NTX = BN / 8;
    constexpr int NTY = BM / 8;
    static_assert(NTX * NTY == 128, "128 threads");

    __shared__ float As[KC * SA];        // k-major: As[k*SA + m]
    __shared__ float Ws[KC * BN];        // n-major: Ws[k*BN + n]

    const float* A  = (SRC == 0) ? Ap : g_a1;
    float*       H  = (SRC == 0) ? g_h1 : g_h2;
    float*       O2 = (SRC == 0) ? g_a1 : o2p;

    const int tid = threadIdx.x;
    const int tx  = tid % NTX;
    const int ty  = tid / NTX;
    const int rowbase = blockIdx.x * BM;

    float acc[8][8] = {};

    for (int kk = 0; kk < K; kk += KC) {
        // --- load A chunk (BM x 32) into k-major As, zero-fill rows >= M ---
        {
            constexpr int PT = (BM * KC / 4) / 128;
            const float4* A4 = (const float4*)A;
#pragma unroll
            for (int t = 0; t < PT; t++) {
                int f  = tid + t * 128;
                int r  = f >> 3;                 // row within tile
                int c4 = f & 7;                  // k-offset / 4
                int grow = rowbase + r;
                float4 v = make_float4(0.f, 0.f, 0.f, 0.f);
                if (grow < M) v = A4[(size_t)grow * 32 + (kk >> 2) + c4];
                if (RELU) {
                    v.x = fmaxf(v.x, 0.f); v.y = fmaxf(v.y, 0.f);
                    v.z = fmaxf(v.z, 0.f); v.w = fmaxf(v.w, 0.f);
                }
                As[(c4 * 4 + 0) * SA + r] = v.x;
                As[(c4 * 4 + 1) * SA + r] = v.y;
                As[(c4 * 4 + 2) * SA + r] = v.z;
                As[(c4 * 4 + 3) * SA + r] = v.w;
            }
        }
        // --- load W chunk (32 x BN) ---
        {
            constexpr int PT = (KC * BN / 4) / 128;
            const float4* W4  = (const float4*)(W + (size_t)kk * BN);
            float4*       Ws4 = (float4*)Ws;
#pragma unroll
            for (int t = 0; t < PT; t++)
                Ws4[tid + t * 128] = W4[tid + t * 128];
        }
        __syncthreads();

#pragma unroll
        for (int k = 0; k < KC; k++) {
            const float4 a0 = *(const float4*)(As + k * SA + ty * 8);
            const float4 a1 = *(const float4*)(As + k * SA + ty * 8 + 4);
            const float4 b0 = ((const float4*)(Ws + k * BN))[tx * 2];
            const float4 b1 = ((const float4*)(Ws + k * BN))[tx * 2 + 1];
            const float a[8] = {a0.x, a0.y, a0.z, a0.w, a1.x, a1.y, a1.z, a1.w};
            const float b[8] = {b0.x, b0.y, b0.z, b0.w, b1.x, b1.y, b1.z, b1.w};
#pragma unroll
            for (int i = 0; i < 8; i++)
#pragma unroll
                for (int j = 0; j < 8; j++)
                    acc[i][j] = fmaf(a[i], b[j], acc[i][j]);
        }
        __syncthreads();
    }

    // --- epilogue: store h and h*dis^2 + bias ---
    const float4 bb0 = ((const float4*)bias)[tx * 2];
    const float4 bb1 = ((const float4*)bias)[tx * 2 + 1];
#pragma unroll
    for (int i = 0; i < 8; i++) {
        int grow = rowbase + ty * 8 + i;
        if (grow < M) {
            float s = g_dis[grow];
            s *= s;
            float4 h0 = make_float4(acc[i][0], acc[i][1], acc[i][2], acc[i][3]);
            float4 h1 = make_float4(acc[i][4], acc[i][5], acc[i][6], acc[i][7]);
            float4* Hr = (float4*)(H + (size_t)grow * BN);
            Hr[tx * 2]     = h0;
            Hr[tx * 2 + 1] = h1;
            float4* Or = (float4*)(O2 + (size_t)grow * BN);
            Or[tx * 2]     = make_float4(fmaf(h0.x, s, bb0.x), fmaf(h0.y, s, bb0.y),
                                         fmaf(h0.z, s, bb0.z), fmaf(h0.w, s, bb0.w));
            Or[tx * 2 + 1] = make_float4(fmaf(h1.x, s, bb1.x), fmaf(h1.y, s, bb1.y),
                                         fmaf(h1.z, s, bb1.z), fmaf(h1.w, s, bb1.w));
        }
    }
}

// ---------------------------------------------------------------------------
// edge scatter: out[dst,:] += dis[src]*dis[dst] * h[src,:]
// one warp per edge; float4/float2 gathers + vectorized L2 reductions
// ---------------------------------------------------------------------------
__device__ __forceinline__ void red_add_v4(float* p, float4 v) {
    asm volatile("red.global.add.v4.f32 [%0], {%1, %2, %3, %4};"
                 :: "l"(p), "f"(v.x), "f"(v.y), "f"(v.z), "f"(v.w)
                 : "memory");
}
__device__ __forceinline__ void red_add_v2(float* p, float a, float b) {
    asm volatile("red.global.add.v2.f32 [%0], {%1, %2};"
                 :: "l"(p), "f"(a), "f"(b)
                 : "memory");
}

template <int C>
__global__ void k_edge(const int* __restrict__ ei, float* __restrict__ outp) {
    const float* h;
    float*       out;
    if constexpr (C == 128) { h = g_h1; out = g_a1; }
    else                    { h = g_h2; out = outp; }

    const int lane = threadIdx.x & 31;
    const int wid  = (blockIdx.x * blockDim.x + threadIdx.x) >> 5;
    const int nw   = (gridDim.x * blockDim.x) >> 5;

    for (int e = wid; e < NE; e += nw) {
        const int s = ei[e];
        const int d = ei[NE + e];
        const float nrm = g_dis[s] * g_dis[d];
        if constexpr (C == 128) {
            float4 v = __ldg((const float4*)h + (size_t)s * 32 + lane);
            red_add_v4(out + (size_t)d * 128 + lane * 4,
                       make_float4(v.x * nrm, v.y * nrm, v.z * nrm, v.w * nrm));
        } else {
            float2 v = __ldg((const float2*)h + (size_t)s * 32 + lane);
            red_add_v2(out + (size_t)d * 64 + lane * 2, v.x * nrm, v.y * nrm);
        }
    }
}

// ---------------------------------------------------------------------------
extern "C" void kernel_launch(void* const* d_in, const int* in_sizes, int n_in,
                              void* d_out, int out_size) {
    (void)in_sizes; (void)n_in; (void)out_size;
    const float* x  = (const float*)d_in[0];
    const int*   ei = (const int*)d_in[1];     // int32 (JAX x64 disabled)
    const float* W1 = (const float*)d_in[2];
    const float* b1 = (const float*)d_in[3];
    const float* W2 = (const float*)d_in[4];
    const float* b2 = (const float*)d_in[5];
    float* out = (float*)d_out;

    // --- normalization ---
    k_deg_init<<<(NN + 255) / 256, 256>>>();
    k_deg_count<<<(NE + 255) / 256, 256>>>(ei);
    k_dis<<<(NN + 255) / 256, 256>>>();

    // --- layer 1: gemm (writes h1 and a1=selfloop+b1), then scatter into a1 ---
    k_gemm<64, 128, false, 0><<<(NN + 63) / 64, 128>>>(x, W1, b1, nullptr, NN);
    k_edge<128><<<1184, 256>>>(ei, nullptr);

    // --- layer 2: gemm reads relu(a1) (writes h2 and out=selfloop+b2), scatter into out ---
    k_gemm<128, 64, true, 1><<<(NN + 127) / 128, 128>>>(nullptr, W2, b2, out, NN);
    k_edge<64><<<1184, 256>>>(ei, out);
}